// round 8
// baseline (speedup 1.0000x reference)
#include <cuda_runtime.h>

#define MCOMP 8
#define SDIM 64
#define NPAIR (SDIM*(SDIM-1)/2)
#define SVS 68            // padded site-vector stride (floats), 16B-aligned, conflict-free
#define TILE_SITES 64

// -------------------- device globals (setup products) --------------------
__device__ float g_Qs[MCOMP][SDIM*SDIM];     // Q * (0.05 / (8*emut))  (pre-scaled for expm)
__device__ float g_pi[MCOMP][SDIM];          // stationary distribution
__device__ float g_Pt[4][MCOMP][SDIM*SDIM];  // transposed transition mats: Pt[k][m][d*64+x] = P_k[m][x][d]

// ==========================================================================
// Kernel 1: build Q (one CTA per mixture component)
// ==========================================================================
__global__ void build_q_kernel(const float* __restrict__ rates,
                               const float* __restrict__ pi_inv)
{
    __shared__ float spi[SDIM];
    __shared__ float srow[SDIM];
    __shared__ float sQ[SDIM*SDIM];
    __shared__ float sns, semut;

    const int m = blockIdx.x;
    const int t = threadIdx.x;
    const float* y = pi_inv + m*(SDIM-1);

    if (t == 0) {
        float ns = 0.f;
        for (int j = 0; j < SDIM-1; j++) { float v = y[j]; ns += v*v; }
        sns = ns;
    }
    __syncthreads();
    const float ns  = sns;
    const float inv = 1.f/(ns + 1.f);
    if (t < SDIM) {
        float p = (t < SDIM-1) ? (2.f*y[t]*inv) : ((ns - 1.f)*inv);
        spi[t] = p*p;
    }
    __syncthreads();

    const float* rm = rates + m*NPAIR;
    for (int idx = t; idx < SDIM*SDIM; idx += 256) {
        int i = idx >> 6, j = idx & 63;
        float v = 0.f;
        if (i != j) {
            int a = i < j ? i : j;
            int b = i < j ? j : i;
            int lin = a*(2*SDIM - a - 1)/2 + (b - a - 1);   // np.triu_indices(S,1) order
            float r = rm[lin];
            v = r*r*spi[j];
        }
        sQ[idx] = v;
    }
    __syncthreads();
    if (t < SDIM) {
        float s = 0.f;
        for (int j = 0; j < SDIM; j++) s += sQ[t*SDIM + j];
        srow[t] = s;
    }
    __syncthreads();
    if (t == 0) {
        float e = 0.f;
        for (int i = 0; i < SDIM; i++) e += spi[i]*srow[i];
        semut = e;
    }
    __syncthreads();
    const float scale = 0.05f/(8.f*semut);   // fold t_base=0.05 and 2^-3 expm scaling
    for (int idx = t; idx < SDIM*SDIM; idx += 256) {
        int i = idx >> 6;
        float v = (i == (idx & 63)) ? -srow[i] : sQ[idx];
        g_Qs[m][idx] = v*scale;
    }
    if (t < SDIM) g_pi[m][t] = spi[t];
}

// ==========================================================================
// Kernel 2: expm via scaling-and-squaring (Taylor-12, s=3) + matrix powers
// ==========================================================================
__device__ __forceinline__ void mm64(const float* __restrict__ A,
                                     const float* __restrict__ B,
                                     float* __restrict__ C, float alpha)
{
    const int t  = threadIdx.x;
    const int j  = t & 63;
    const int rg = t >> 6;        // 0..3 (16 rows each)
    float c[16];
#pragma unroll
    for (int ii = 0; ii < 16; ii++) c[ii] = 0.f;
    for (int d = 0; d < SDIM; d++) {
        float b = B[d*SDIM + j];
#pragma unroll
        for (int ii = 0; ii < 16; ii++)
            c[ii] += A[(rg*16 + ii)*SDIM + d]*b;
    }
#pragma unroll
    for (int ii = 0; ii < 16; ii++) C[(rg*16 + ii)*SDIM + j] = alpha*c[ii];
}

__device__ __forceinline__ void storeT(int k, int m, const float* __restrict__ buf)
{
    const int t = threadIdx.x;
    for (int idx = t; idx < SDIM*SDIM; idx += 256) {
        int d = idx >> 6, x = idx & 63;
        g_Pt[k][m][idx] = buf[x*SDIM + d];
    }
}

__global__ void expm_kernel()
{
    extern __shared__ float sm[];
    float* Bm  = sm;
    float* sum = sm + 4096;
    float* b0  = sm + 2*4096;
    float* b1  = sm + 3*4096;

    const int m = blockIdx.x;
    const int t = threadIdx.x;

    for (int idx = t; idx < 4096; idx += 256) {
        float b = g_Qs[m][idx];
        int i = idx >> 6, j = idx & 63;
        Bm[idx]  = b;
        sum[idx] = b + (i == j ? 1.f : 0.f);   // I + B
        b0[idx]  = b;                          // term = B
    }
    __syncthreads();

    float* cur = b0;
    float* nxt = b1;
    for (int k = 2; k <= 12; k++) {            // Taylor series of exp(B), ||B|| < ~0.15
        mm64(cur, Bm, nxt, 1.f/(float)k);
        __syncthreads();
        for (int idx = t; idx < 4096; idx += 256) sum[idx] += nxt[idx];
        float* tmp = cur; cur = nxt; nxt = tmp;
        __syncthreads();
    }
    // 3 squarings: sum <- sum^8 = expm(0.05*Q) = P1
    mm64(sum, sum, cur, 1.f); __syncthreads();
    mm64(cur, cur, nxt, 1.f); __syncthreads();
    mm64(nxt, nxt, sum, 1.f); __syncthreads();
    storeT(0, m, sum);                          // P1 (t=0.05)
    __syncthreads();
    mm64(sum, sum, cur, 1.f); __syncthreads();  // cur = P2
    storeT(1, m, cur);                          // P2 (t=0.10)
    __syncthreads();
    mm64(cur, sum, nxt, 1.f); __syncthreads();  // nxt = P3 = P2*P1
    storeT(2, m, nxt);                          // P3 (t=0.15)
    __syncthreads();
    mm64(cur, cur, nxt, 1.f); __syncthreads();  // nxt = P4 = P2*P2
    storeT(3, m, nxt);                          // P4 (t=0.20)
}

// ==========================================================================
// Kernel 3: fused Felsenstein pruning over the whole tree, per (m, 64-site tile)
// Thread layout: x4 = tid&15 -> states [4*x4, 4*x4+3]; sl = tid>>4 -> 4 sites each
// ==========================================================================
__device__ __forceinline__ void stage_leaf(const float* __restrict__ X, float* __restrict__ buf,
                                           int s0, int leaf, int nsites, int t)
{
    for (int idx = t; idx < 1024; idx += 256) {
        int ls = idx >> 4;
        int c4 = idx & 15;
        int site = s0 + ls;
        float4 v = make_float4(0.f, 0.f, 0.f, 0.f);
        if (site < nsites)
            v = *(const float4*)(X + ((size_t)site*8 + leaf)*64 + c4*4);
        *(float4*)(buf + ls*SVS + c4*4) = v;
    }
}

__device__ __forceinline__ void node_msgs(const float* __restrict__ sPt,
                                          int k0, int k1,
                                          const float* __restrict__ v0,
                                          const float* __restrict__ v1,
                                          int x4, int lsb,
                                          float4 a0[4], float4 a1[4])
{
#pragma unroll
    for (int sb = 0; sb < 4; sb++) {
        a0[sb] = make_float4(0.f, 0.f, 0.f, 0.f);
        a1[sb] = make_float4(0.f, 0.f, 0.f, 0.f);
    }
    const float* P0 = sPt + k0*4096 + 4*x4;
    const float* P1 = sPt + k1*4096 + 4*x4;
#pragma unroll 4
    for (int d = 0; d < SDIM; d++) {
        float4 p0 = *(const float4*)(P0 + d*SDIM);
        float4 p1 = *(const float4*)(P1 + d*SDIM);
#pragma unroll
        for (int sb = 0; sb < 4; sb++) {
            float w0 = v0[(lsb + sb)*SVS + d];
            float w1 = v1[(lsb + sb)*SVS + d];
            a0[sb].x += p0.x*w0; a0[sb].y += p0.y*w0; a0[sb].z += p0.z*w0; a0[sb].w += p0.w*w0;
            a1[sb].x += p1.x*w1; a1[sb].y += p1.y*w1; a1[sb].z += p1.z*w1; a1[sb].w += p1.w*w1;
        }
    }
}

__global__ __launch_bounds__(256, 1)
void tree_kernel(const float* __restrict__ X, float* __restrict__ out, int nsites)
{
    extern __shared__ float sm[];
    float* sPt = sm;                       // 4 * 4096 floats (P1..P4 transposed)
    float* sV0 = sPt + 4*4096;             // 64*SVS
    float* sV1 = sV0 + SDIM*SVS;
    float* sA  = sV1 + SDIM*SVS;           // 4 * 64*SVS (level-1 messages)
    float* spi = sA + 4*SDIM*SVS;          // 64

    const int m   = blockIdx.y;
    const int s0  = blockIdx.x * TILE_SITES;
    const int t   = threadIdx.x;
    const int x4  = t & 15;
    const int sl  = t >> 4;
    const int lsb = sl * 4;

    // load all 4 P matrices (transposed) + pi for this component
    for (int idx = t; idx < 4*1024; idx += 256) {
        int k   = idx >> 10;
        int off = idx & 1023;
        ((float4*)sPt)[k*1024 + off] = ((const float4*)g_Pt[k][m])[off];
    }
    if (t < SDIM) spi[t] = g_pi[m][t];
    __syncthreads();

    // ---- level 1: nodes 8..11 (leaf pairs) ----
    for (int nn = 0; nn < 4; nn++) {
        stage_leaf(X, sV0, s0, 2*nn,   nsites, t);
        stage_leaf(X, sV1, s0, 2*nn+1, nsites, t);
        __syncthreads();
        float4 a0[4], a1[4];
        int k0 = (nn & 1)*2;               // nodes 8,10 -> (P1,P2); nodes 9,11 -> (P3,P4)
        node_msgs(sPt, k0, k0+1, sV0, sV1, x4, lsb, a0, a1);
        float* ob = sA + nn*SDIM*SVS;
#pragma unroll
        for (int sb = 0; sb < 4; sb++) {
            float4 r;
            r.x = a0[sb].x*a1[sb].x; r.y = a0[sb].y*a1[sb].y;
            r.z = a0[sb].z*a1[sb].z; r.w = a0[sb].w*a1[sb].w;
            *(float4*)(ob + (lsb + sb)*SVS + 4*x4) = r;
        }
        __syncthreads();
    }

    // ---- level 2: node 12 (A8,A9; P1,P2) -> sV0, node 13 (A10,A11; P3,P4) -> sV1 ----
    {
        float4 a0[4], a1[4];
        node_msgs(sPt, 0, 1, sA, sA + SDIM*SVS, x4, lsb, a0, a1);
#pragma unroll
        for (int sb = 0; sb < 4; sb++) {
            float4 r;
            r.x = a0[sb].x*a1[sb].x; r.y = a0[sb].y*a1[sb].y;
            r.z = a0[sb].z*a1[sb].z; r.w = a0[sb].w*a1[sb].w;
            *(float4*)(sV0 + (lsb + sb)*SVS + 4*x4) = r;
        }
        node_msgs(sPt, 2, 3, sA + 2*SDIM*SVS, sA + 3*SDIM*SVS, x4, lsb, a0, a1);
#pragma unroll
        for (int sb = 0; sb < 4; sb++) {
            float4 r;
            r.x = a0[sb].x*a1[sb].x; r.y = a0[sb].y*a1[sb].y;
            r.z = a0[sb].z*a1[sb].z; r.w = a0[sb].w*a1[sb].w;
            *(float4*)(sV1 + (lsb + sb)*SVS + 4*x4) = r;
        }
        __syncthreads();
    }

    // ---- level 3: root node 14 (A12,A13; P1,P2) + marginalize against pi ----
    {
        float4 a0[4], a1[4];
        node_msgs(sPt, 0, 1, sV0, sV1, x4, lsb, a0, a1);
        float4 pv = *(const float4*)(spi + 4*x4);
#pragma unroll
        for (int sb = 0; sb < 4; sb++) {
            float p = (a0[sb].x*a1[sb].x)*pv.x + (a0[sb].y*a1[sb].y)*pv.y
                    + (a0[sb].z*a1[sb].z)*pv.z + (a0[sb].w*a1[sb].w)*pv.w;
            // reduce over the 16 state-threads (contiguous 16-lane segments)
            p += __shfl_down_sync(0xffffffffu, p, 8, 16);
            p += __shfl_down_sync(0xffffffffu, p, 4, 16);
            p += __shfl_down_sync(0xffffffffu, p, 2, 16);
            p += __shfl_down_sync(0xffffffffu, p, 1, 16);
            int site = s0 + lsb + sb;
            if (x4 == 0 && site < nsites)
                out[(size_t)site*MCOMP + m] = p;
        }
    }
}

// ==========================================================================
// kernel_launch
// ==========================================================================
extern "C" void kernel_launch(void* const* d_in, const int* in_sizes, int n_in,
                              void* d_out, int out_size)
{
    const float* X      = (const float*)d_in[0];
    const float* rates  = (const float*)d_in[1];
    const float* pi_inv = (const float*)d_in[2];
    float* out = (float*)d_out;
    const int nsites = in_sizes[0] / (8*64);

    const size_t expm_smem = 4*4096*sizeof(float);                       // 64 KB
    const size_t tree_smem = (4*4096 + 6*SDIM*SVS + 64)*sizeof(float);   // ~166 KB

    // idempotent; ignore errors (already set from the first, non-captured call)
    cudaFuncSetAttribute(expm_kernel, cudaFuncAttributeMaxDynamicSharedMemorySize, (int)expm_smem);
    cudaFuncSetAttribute(tree_kernel, cudaFuncAttributeMaxDynamicSharedMemorySize, (int)tree_smem);

    build_q_kernel<<<MCOMP, 256>>>(rates, pi_inv);
    expm_kernel<<<MCOMP, 256, expm_smem>>>();

    dim3 grid((nsites + TILE_SITES - 1)/TILE_SITES, MCOMP);
    tree_kernel<<<grid, 256, tree_smem>>>(X, out, nsites);
}

// round 9
// speedup vs baseline: 1.0092x; 1.0092x over previous
#include <cuda_runtime.h>

#define MCOMP 8
#define SDIM 64
#define NPAIR (SDIM*(SDIM-1)/2)
#define SVS 68            // padded site-vector stride (floats), 16B-aligned, conflict-free
#define TILE_SITES 64

// -------------------- device globals (setup products) --------------------
__device__ float g_Qs[MCOMP][SDIM*SDIM];     // Q * (0.05 / (8*emut))  (pre-scaled for expm)
__device__ float g_pi[MCOMP][SDIM];          // stationary distribution
__device__ float g_Pt[4][MCOMP][SDIM*SDIM];  // transposed transition mats: Pt[k][m][d*64+x] = P_k[m][x][d]

// ==========================================================================
// Kernel 1: build Q (one CTA per mixture component)
// ==========================================================================
__global__ void build_q_kernel(const float* __restrict__ rates,
                               const float* __restrict__ pi_inv)
{
    __shared__ float spi[SDIM];
    __shared__ float srow[SDIM];
    __shared__ float sQ[SDIM*SDIM];
    __shared__ float sns, semut;

    const int m = blockIdx.x;
    const int t = threadIdx.x;
    const float* y = pi_inv + m*(SDIM-1);

    if (t == 0) {
        float ns = 0.f;
        for (int j = 0; j < SDIM-1; j++) { float v = y[j]; ns += v*v; }
        sns = ns;
    }
    __syncthreads();
    const float ns  = sns;
    const float inv = 1.f/(ns + 1.f);
    if (t < SDIM) {
        float p = (t < SDIM-1) ? (2.f*y[t]*inv) : ((ns - 1.f)*inv);
        spi[t] = p*p;
    }
    __syncthreads();

    const float* rm = rates + m*NPAIR;
    for (int idx = t; idx < SDIM*SDIM; idx += 256) {
        int i = idx >> 6, j = idx & 63;
        float v = 0.f;
        if (i != j) {
            int a = i < j ? i : j;
            int b = i < j ? j : i;
            int lin = a*(2*SDIM - a - 1)/2 + (b - a - 1);   // np.triu_indices(S,1) order
            float r = rm[lin];
            v = r*r*spi[j];
        }
        sQ[idx] = v;
    }
    __syncthreads();
    if (t < SDIM) {
        float s = 0.f;
        for (int j = 0; j < SDIM; j++) s += sQ[t*SDIM + j];
        srow[t] = s;
    }
    __syncthreads();
    if (t == 0) {
        float e = 0.f;
        for (int i = 0; i < SDIM; i++) e += spi[i]*srow[i];
        semut = e;
    }
    __syncthreads();
    const float scale = 0.05f/(8.f*semut);   // fold t_base=0.05 and 2^-3 expm scaling
    for (int idx = t; idx < SDIM*SDIM; idx += 256) {
        int i = idx >> 6;
        float v = (i == (idx & 63)) ? -srow[i] : sQ[idx];
        g_Qs[m][idx] = v*scale;
    }
    if (t < SDIM) g_pi[m][t] = spi[t];
}

// ==========================================================================
// Kernel 2: expm via scaling-and-squaring (Taylor-12, s=3) + matrix powers
// ==========================================================================
__device__ __forceinline__ void mm64(const float* __restrict__ A,
                                     const float* __restrict__ B,
                                     float* __restrict__ C, float alpha)
{
    const int t  = threadIdx.x;
    const int j  = t & 63;
    const int rg = t >> 6;        // 0..3 (16 rows each)
    float c[16];
#pragma unroll
    for (int ii = 0; ii < 16; ii++) c[ii] = 0.f;
    for (int d = 0; d < SDIM; d++) {
        float b = B[d*SDIM + j];
#pragma unroll
        for (int ii = 0; ii < 16; ii++)
            c[ii] += A[(rg*16 + ii)*SDIM + d]*b;
    }
#pragma unroll
    for (int ii = 0; ii < 16; ii++) C[(rg*16 + ii)*SDIM + j] = alpha*c[ii];
}

__device__ __forceinline__ void storeT(int k, int m, const float* __restrict__ buf)
{
    const int t = threadIdx.x;
    for (int idx = t; idx < SDIM*SDIM; idx += 256) {
        int d = idx >> 6, x = idx & 63;
        g_Pt[k][m][idx] = buf[x*SDIM + d];
    }
}

__global__ void expm_kernel()
{
    extern __shared__ float sm[];
    float* Bm  = sm;
    float* sum = sm + 4096;
    float* b0  = sm + 2*4096;
    float* b1  = sm + 3*4096;

    const int m = blockIdx.x;
    const int t = threadIdx.x;

    for (int idx = t; idx < 4096; idx += 256) {
        float b = g_Qs[m][idx];
        int i = idx >> 6, j = idx & 63;
        Bm[idx]  = b;
        sum[idx] = b + (i == j ? 1.f : 0.f);   // I + B
        b0[idx]  = b;                          // term = B
    }
    __syncthreads();

    float* cur = b0;
    float* nxt = b1;
    for (int k = 2; k <= 12; k++) {            // Taylor series of exp(B), ||B|| < ~0.15
        mm64(cur, Bm, nxt, 1.f/(float)k);
        __syncthreads();
        for (int idx = t; idx < 4096; idx += 256) sum[idx] += nxt[idx];
        float* tmp = cur; cur = nxt; nxt = tmp;
        __syncthreads();
    }
    // 3 squarings: sum <- sum^8 = expm(0.05*Q) = P1
    mm64(sum, sum, cur, 1.f); __syncthreads();
    mm64(cur, cur, nxt, 1.f); __syncthreads();
    mm64(nxt, nxt, sum, 1.f); __syncthreads();
    storeT(0, m, sum);                          // P1 (t=0.05)
    __syncthreads();
    mm64(sum, sum, cur, 1.f); __syncthreads();  // cur = P2
    storeT(1, m, cur);                          // P2 (t=0.10)
    __syncthreads();
    mm64(cur, sum, nxt, 1.f); __syncthreads();  // nxt = P3 = P2*P1
    storeT(2, m, nxt);                          // P3 (t=0.15)
    __syncthreads();
    mm64(cur, cur, nxt, 1.f); __syncthreads();  // nxt = P4 = P2*P2
    storeT(3, m, nxt);                          // P4 (t=0.20)
}

// ==========================================================================
// Kernel 3: fused Felsenstein pruning over the whole tree, per (m, 64-site tile)
// Thread layout: x4 = tid&15 -> states [4*x4, 4*x4+3]; sl = tid>>4 -> 4 sites each
// ==========================================================================
__device__ __forceinline__ void stage_leaf(const float* __restrict__ X, float* __restrict__ buf,
                                           int s0, int leaf, int nsites, int t)
{
    for (int idx = t; idx < 1024; idx += 256) {
        int ls = idx >> 4;
        int c4 = idx & 15;
        int site = s0 + ls;
        float4 v = make_float4(0.f, 0.f, 0.f, 0.f);
        if (site < nsites)
            v = *(const float4*)(X + ((size_t)site*8 + leaf)*64 + c4*4);
        *(float4*)(buf + ls*SVS + c4*4) = v;
    }
}

__device__ __forceinline__ void node_msgs(const float* __restrict__ sPt,
                                          int k0, int k1,
                                          const float* __restrict__ v0,
                                          const float* __restrict__ v1,
                                          int x4, int lsb,
                                          float4 a0[4], float4 a1[4])
{
#pragma unroll
    for (int sb = 0; sb < 4; sb++) {
        a0[sb] = make_float4(0.f, 0.f, 0.f, 0.f);
        a1[sb] = make_float4(0.f, 0.f, 0.f, 0.f);
    }
    const float* P0 = sPt + k0*4096 + 4*x4;
    const float* P1 = sPt + k1*4096 + 4*x4;
#pragma unroll 4
    for (int d = 0; d < SDIM; d++) {
        float4 p0 = *(const float4*)(P0 + d*SDIM);
        float4 p1 = *(const float4*)(P1 + d*SDIM);
#pragma unroll
        for (int sb = 0; sb < 4; sb++) {
            float w0 = v0[(lsb + sb)*SVS + d];
            float w1 = v1[(lsb + sb)*SVS + d];
            a0[sb].x += p0.x*w0; a0[sb].y += p0.y*w0; a0[sb].z += p0.z*w0; a0[sb].w += p0.w*w0;
            a1[sb].x += p1.x*w1; a1[sb].y += p1.y*w1; a1[sb].z += p1.z*w1; a1[sb].w += p1.w*w1;
        }
    }
}

__global__ __launch_bounds__(256, 1)
void tree_kernel(const float* __restrict__ X, float* __restrict__ out, int nsites)
{
    extern __shared__ float sm[];
    float* sPt = sm;                       // 4 * 4096 floats (P1..P4 transposed)
    float* sV0 = sPt + 4*4096;             // 64*SVS
    float* sV1 = sV0 + SDIM*SVS;
    float* sA  = sV1 + SDIM*SVS;           // 4 * 64*SVS (level-1 messages)
    float* spi = sA + 4*SDIM*SVS;          // 64

    const int m   = blockIdx.y;
    const int s0  = blockIdx.x * TILE_SITES;
    const int t   = threadIdx.x;
    const int x4  = t & 15;
    const int sl  = t >> 4;
    const int lsb = sl * 4;

    // load all 4 P matrices (transposed) + pi for this component
    for (int idx = t; idx < 4*1024; idx += 256) {
        int k   = idx >> 10;
        int off = idx & 1023;
        ((float4*)sPt)[k*1024 + off] = ((const float4*)g_Pt[k][m])[off];
    }
    if (t < SDIM) spi[t] = g_pi[m][t];
    __syncthreads();

    // ---- level 1: nodes 8..11 (leaf pairs) ----
    for (int nn = 0; nn < 4; nn++) {
        stage_leaf(X, sV0, s0, 2*nn,   nsites, t);
        stage_leaf(X, sV1, s0, 2*nn+1, nsites, t);
        __syncthreads();
        float4 a0[4], a1[4];
        int k0 = (nn & 1)*2;               // nodes 8,10 -> (P1,P2); nodes 9,11 -> (P3,P4)
        node_msgs(sPt, k0, k0+1, sV0, sV1, x4, lsb, a0, a1);
        float* ob = sA + nn*SDIM*SVS;
#pragma unroll
        for (int sb = 0; sb < 4; sb++) {
            float4 r;
            r.x = a0[sb].x*a1[sb].x; r.y = a0[sb].y*a1[sb].y;
            r.z = a0[sb].z*a1[sb].z; r.w = a0[sb].w*a1[sb].w;
            *(float4*)(ob + (lsb + sb)*SVS + 4*x4) = r;
        }
        __syncthreads();
    }

    // ---- level 2: node 12 (A8,A9; P1,P2) -> sV0, node 13 (A10,A11; P3,P4) -> sV1 ----
    {
        float4 a0[4], a1[4];
        node_msgs(sPt, 0, 1, sA, sA + SDIM*SVS, x4, lsb, a0, a1);
#pragma unroll
        for (int sb = 0; sb < 4; sb++) {
            float4 r;
            r.x = a0[sb].x*a1[sb].x; r.y = a0[sb].y*a1[sb].y;
            r.z = a0[sb].z*a1[sb].z; r.w = a0[sb].w*a1[sb].w;
            *(float4*)(sV0 + (lsb + sb)*SVS + 4*x4) = r;
        }
        node_msgs(sPt, 2, 3, sA + 2*SDIM*SVS, sA + 3*SDIM*SVS, x4, lsb, a0, a1);
#pragma unroll
        for (int sb = 0; sb < 4; sb++) {
            float4 r;
            r.x = a0[sb].x*a1[sb].x; r.y = a0[sb].y*a1[sb].y;
            r.z = a0[sb].z*a1[sb].z; r.w = a0[sb].w*a1[sb].w;
            *(float4*)(sV1 + (lsb + sb)*SVS + 4*x4) = r;
        }
        __syncthreads();
    }

    // ---- level 3: root node 14 (A12,A13; P1,P2) + marginalize against pi ----
    {
        float4 a0[4], a1[4];
        node_msgs(sPt, 0, 1, sV0, sV1, x4, lsb, a0, a1);
        float4 pv = *(const float4*)(spi + 4*x4);
#pragma unroll
        for (int sb = 0; sb < 4; sb++) {
            float p = (a0[sb].x*a1[sb].x)*pv.x + (a0[sb].y*a1[sb].y)*pv.y
                    + (a0[sb].z*a1[sb].z)*pv.z + (a0[sb].w*a1[sb].w)*pv.w;
            // reduce over the 16 state-threads (contiguous 16-lane segments)
            p += __shfl_down_sync(0xffffffffu, p, 8, 16);
            p += __shfl_down_sync(0xffffffffu, p, 4, 16);
            p += __shfl_down_sync(0xffffffffu, p, 2, 16);
            p += __shfl_down_sync(0xffffffffu, p, 1, 16);
            int site = s0 + lsb + sb;
            if (x4 == 0 && site < nsites)
                out[(size_t)site*MCOMP + m] = p;
        }
    }
}

// ==========================================================================
// kernel_launch
// ==========================================================================
extern "C" void kernel_launch(void* const* d_in, const int* in_sizes, int n_in,
                              void* d_out, int out_size)
{
    const float* X      = (const float*)d_in[0];
    const float* rates  = (const float*)d_in[1];
    const float* pi_inv = (const float*)d_in[2];
    float* out = (float*)d_out;
    const int nsites = in_sizes[0] / (8*64);

    const size_t expm_smem = 4*4096*sizeof(float);                       // 64 KB
    const size_t tree_smem = (4*4096 + 6*SDIM*SVS + 64)*sizeof(float);   // ~166 KB

    // idempotent; ignore errors (already set from the first, non-captured call)
    cudaFuncSetAttribute(expm_kernel, cudaFuncAttributeMaxDynamicSharedMemorySize, (int)expm_smem);
    cudaFuncSetAttribute(tree_kernel, cudaFuncAttributeMaxDynamicSharedMemorySize, (int)tree_smem);

    build_q_kernel<<<MCOMP, 256>>>(rates, pi_inv);
    expm_kernel<<<MCOMP, 256, expm_smem>>>();

    dim3 grid((nsites + TILE_SITES - 1)/TILE_SITES, MCOMP);
    tree_kernel<<<grid, 256, tree_smem>>>(X, out, nsites);
}

// round 12
// speedup vs baseline: 1.2540x; 1.2426x over previous
#include <cuda_runtime.h>
#include <cuda_bf16.h>
#include <cstdint>

#define MCOMP 8
#define SDIM 64
#define NPAIR (SDIM*(SDIM-1)/2)

// -------------------- device globals (setup products) --------------------
__device__ float g_Qs[MCOMP][SDIM*SDIM];                 // Q * (0.05/(8*emut))
__device__ float g_pi[MCOMP][SDIM];                      // stationary distribution
// P matrices row-major [c][d] as packed bf16 pairs (u32), hi and lo planes
__device__ __align__(16) uint32_t g_Ph[4][MCOMP][2048];
__device__ __align__(16) uint32_t g_Pl[4][MCOMP][2048];

// single shared dynamic-smem symbol for all kernels in this TU
extern __shared__ char dyn_smem[];

// -------------------- helpers --------------------
__device__ __forceinline__ uint32_t pack2(__nv_bfloat16 a, __nv_bfloat16 b) {
    return (uint32_t)__bfloat16_as_ushort(a) | ((uint32_t)__bfloat16_as_ushort(b) << 16);
}
__device__ __forceinline__ void split_pair(float a, float b, uint32_t& hi, uint32_t& lo) {
    __nv_bfloat16 ha = __float2bfloat16(a), hb = __float2bfloat16(b);
    __nv_bfloat16 la = __float2bfloat16(a - __bfloat162float(ha));
    __nv_bfloat16 lb = __float2bfloat16(b - __bfloat162float(hb));
    hi = pack2(ha, hb);
    lo = pack2(la, lb);
}

__device__ __forceinline__ void mma16816(float& c0, float& c1, float& c2, float& c3,
                                         uint32_t a0, uint32_t a1, uint32_t a2, uint32_t a3,
                                         uint32_t b0, uint32_t b1) {
    asm volatile(
        "mma.sync.aligned.m16n8k16.row.col.f32.bf16.bf16.f32 "
        "{%0,%1,%2,%3}, {%4,%5,%6,%7}, {%8,%9}, {%0,%1,%2,%3};"
        : "+f"(c0), "+f"(c1), "+f"(c2), "+f"(c3)
        : "r"(a0), "r"(a1), "r"(a2), "r"(a3), "r"(b0), "r"(b1));
}

// ==========================================================================
// Kernel 1: build Q (one CTA per component)
// ==========================================================================
__global__ void build_q_kernel(const float* __restrict__ rates,
                               const float* __restrict__ pi_inv)
{
    __shared__ float spi[SDIM];
    __shared__ float srow[SDIM];
    __shared__ float sQ[SDIM*SDIM];
    __shared__ float sns, semut;

    const int m = blockIdx.x;
    const int t = threadIdx.x;
    const float* y = pi_inv + m*(SDIM-1);

    if (t == 0) {
        float ns = 0.f;
        for (int j = 0; j < SDIM-1; j++) { float v = y[j]; ns += v*v; }
        sns = ns;
    }
    __syncthreads();
    const float ns  = sns;
    const float inv = 1.f/(ns + 1.f);
    if (t < SDIM) {
        float p = (t < SDIM-1) ? (2.f*y[t]*inv) : ((ns - 1.f)*inv);
        spi[t] = p*p;
    }
    __syncthreads();

    const float* rm = rates + m*NPAIR;
    for (int idx = t; idx < SDIM*SDIM; idx += 256) {
        int i = idx >> 6, j = idx & 63;
        float v = 0.f;
        if (i != j) {
            int a = i < j ? i : j;
            int b = i < j ? j : i;
            int lin = a*(2*SDIM - a - 1)/2 + (b - a - 1);   // np.triu_indices order
            float r = rm[lin];
            v = r*r*spi[j];
        }
        sQ[idx] = v;
    }
    __syncthreads();
    if (t < SDIM) {
        float s = 0.f;
        for (int j = 0; j < SDIM; j++) s += sQ[t*SDIM + j];
        srow[t] = s;
    }
    __syncthreads();
    if (t == 0) {
        float e = 0.f;
        for (int i = 0; i < SDIM; i++) e += spi[i]*srow[i];
        semut = e;
    }
    __syncthreads();
    const float scale = 0.05f/(8.f*semut);   // fold t_base=0.05 and 2^-3 expm scaling
    for (int idx = t; idx < SDIM*SDIM; idx += 256) {
        int i = idx >> 6;
        float v = (i == (idx & 63)) ? -srow[i] : sQ[idx];
        g_Qs[m][idx] = v*scale;
    }
    if (t < SDIM) g_pi[m][t] = spi[t];
}

// ==========================================================================
// Kernel 2: expm (Taylor-12, s=3) + matrix powers; outputs split-bf16 planes
// ==========================================================================
__device__ __forceinline__ void mm64(const float* __restrict__ A,
                                     const float* __restrict__ B,
                                     float* __restrict__ C, float alpha)
{
    const int t  = threadIdx.x;
    const int j  = t & 63;
    const int rg = t >> 6;
    float c[16];
#pragma unroll
    for (int ii = 0; ii < 16; ii++) c[ii] = 0.f;
    for (int d = 0; d < SDIM; d++) {
        float b = B[d*SDIM + j];
#pragma unroll
        for (int ii = 0; ii < 16; ii++)
            c[ii] += A[(rg*16 + ii)*SDIM + d]*b;
    }
#pragma unroll
    for (int ii = 0; ii < 16; ii++) C[(rg*16 + ii)*SDIM + j] = alpha*c[ii];
}

__device__ __forceinline__ void storeP(int k, int m, const float* __restrict__ buf)
{
    const int t = threadIdx.x;
    for (int idx = t; idx < 2048; idx += 256) {
        int c = idx >> 5, d = (idx & 31)*2;       // row-major [c][d], d contiguous
        uint32_t hi, lo;
        split_pair(buf[c*64 + d], buf[c*64 + d + 1], hi, lo);
        g_Ph[k][m][idx] = hi;
        g_Pl[k][m][idx] = lo;
    }
}

__global__ void expm_kernel()
{
    float* smf = (float*)dyn_smem;
    float* Bm  = smf;
    float* sum = smf + 4096;
    float* b0  = smf + 2*4096;
    float* b1  = smf + 3*4096;

    const int m = blockIdx.x;
    const int t = threadIdx.x;

    for (int idx = t; idx < 4096; idx += 256) {
        float b = g_Qs[m][idx];
        int i = idx >> 6, j = idx & 63;
        Bm[idx]  = b;
        sum[idx] = b + (i == j ? 1.f : 0.f);
        b0[idx]  = b;
    }
    __syncthreads();

    float* cur = b0;
    float* nxt = b1;
    for (int k = 2; k <= 12; k++) {
        mm64(cur, Bm, nxt, 1.f/(float)k);
        __syncthreads();
        for (int idx = t; idx < 4096; idx += 256) sum[idx] += nxt[idx];
        float* tmp = cur; cur = nxt; nxt = tmp;
        __syncthreads();
    }
    mm64(sum, sum, cur, 1.f); __syncthreads();
    mm64(cur, cur, nxt, 1.f); __syncthreads();
    mm64(nxt, nxt, sum, 1.f); __syncthreads();
    storeP(0, m, sum);                          // P1 (t=0.05)
    __syncthreads();
    mm64(sum, sum, cur, 1.f); __syncthreads();  // cur = P2
    storeP(1, m, cur);
    __syncthreads();
    mm64(cur, sum, nxt, 1.f); __syncthreads();  // nxt = P3 = P2*P1
    storeP(2, m, nxt);
    __syncthreads();
    mm64(cur, cur, nxt, 1.f); __syncthreads();  // nxt = P4 = P2*P2
    storeP(3, m, nxt);
}

// ==========================================================================
// Kernel 3: mma.sync Felsenstein pruning. One CTA = (component, 128-site tile)
//
// SMEM layout (row stride = 72 bf16 = 144B = 36 words; 36 % 32 == 4 so the
// 8 fragment rows map to disjoint bank groups -> conflict-free LDS/STS):
//   P mats:   4 x (hi 64x72 + lo 64x72) bf16 = 73728 B
//   buffers:  V0 V1 Ma Mb, each 128x72 bf16 hi + lo = 4 x 36864 B
//   pi:       64 floats
// ==========================================================================
#define RS     72                    // row stride in bf16 elems
#define ROWB   144                   // row stride bytes
#define PHALF  (64*ROWB)             // 9216
#define PMAT   (2*PHALF)             // 18432
#define VHALF  (128*ROWB)            // 18432
#define VBUF   (2*VHALF)             // 36864
#define OFF_P   0u
#define OFF_V0  (4u*PMAT)            // 73728
#define OFF_V1  (OFF_V0 + VBUF)
#define OFF_MA  (OFF_V1 + VBUF)
#define OFF_MB  (OFF_MA + VBUF)
#define OFF_PI  (OFF_MB + VBUF)      // 221184
#define SMEM_TREE (OFF_PI + 256u)    // 221440

// one child matvec: acc[n][0..3] += (V @ P^T) for this warp's 16 site-rows
__device__ __forceinline__ void matvec(const char* sm, uint32_t voff, uint32_t poff,
                                       float acc[8][4], int w, int lane)
{
    const int g  = lane >> 2;
    const int i2 = (lane & 3)*2;
#pragma unroll 1
    for (int ks = 0; ks < 4; ks++) {
        const uint32_t abase = voff + (uint32_t)((w*16 + g)*RS + ks*16 + i2)*2u;
        uint32_t ah0 = *(const uint32_t*)(sm + abase);
        uint32_t ah1 = *(const uint32_t*)(sm + abase + 8*ROWB);
        uint32_t ah2 = *(const uint32_t*)(sm + abase + 16);
        uint32_t ah3 = *(const uint32_t*)(sm + abase + 8*ROWB + 16);
        uint32_t al0 = *(const uint32_t*)(sm + abase + VHALF);
        uint32_t al1 = *(const uint32_t*)(sm + abase + VHALF + 8*ROWB);
        uint32_t al2 = *(const uint32_t*)(sm + abase + VHALF + 16);
        uint32_t al3 = *(const uint32_t*)(sm + abase + VHALF + 8*ROWB + 16);
#pragma unroll
        for (int n = 0; n < 8; n++) {
            const uint32_t bbase = poff + (uint32_t)((n*8 + g)*RS + ks*16 + i2)*2u;
            uint32_t bh0 = *(const uint32_t*)(sm + bbase);
            uint32_t bh1 = *(const uint32_t*)(sm + bbase + 16);
            uint32_t bl0 = *(const uint32_t*)(sm + bbase + PHALF);
            uint32_t bl1 = *(const uint32_t*)(sm + bbase + PHALF + 16);
            mma16816(acc[n][0], acc[n][1], acc[n][2], acc[n][3], ah0, ah1, ah2, ah3, bh0, bh1);
            mma16816(acc[n][0], acc[n][1], acc[n][2], acc[n][3], al0, al1, al2, al3, bh0, bh1);
            mma16816(acc[n][0], acc[n][1], acc[n][2], acc[n][3], ah0, ah1, ah2, ah3, bl0, bl1);
        }
    }
}

// full internal node: two child matvecs, elementwise product, split-store to dst
__device__ __forceinline__ void do_node(char* sm, uint32_t v0, int k0, uint32_t v1, int k1,
                                        uint32_t dst, int w, int lane)
{
    float acc0[8][4], acc1[8][4];
#pragma unroll
    for (int n = 0; n < 8; n++)
#pragma unroll
        for (int q = 0; q < 4; q++) { acc0[n][q] = 0.f; acc1[n][q] = 0.f; }

    matvec(sm, v0, OFF_P + (uint32_t)k0*PMAT, acc0, w, lane);
    matvec(sm, v1, OFF_P + (uint32_t)k1*PMAT, acc1, w, lane);

    const int g  = lane >> 2;
    const int i2 = (lane & 3)*2;
#pragma unroll
    for (int n = 0; n < 8; n++) {
#pragma unroll
        for (int h = 0; h < 2; h++) {
            float p0 = acc0[n][h*2]   * acc1[n][h*2];
            float p1 = acc0[n][h*2+1] * acc1[n][h*2+1];
            uint32_t hi, lo;
            split_pair(p0, p1, hi, lo);
            uint32_t off = (uint32_t)((w*16 + g + h*8)*RS + n*8 + i2)*2u;
            *(uint32_t*)(sm + dst + off)         = hi;
            *(uint32_t*)(sm + dst + VHALF + off) = lo;
        }
    }
    __syncwarp();
}

// stage one leaf's 16 warp-rows into a buffer (split to bf16 hi/lo planes)
__device__ __forceinline__ void stage_leaf(const float* __restrict__ X, char* sm,
                                           uint32_t dst, int s0, int leaf, int nsites,
                                           int w, int lane)
{
#pragma unroll 1
    for (int r = 0; r < 16; r++) {
        int row  = w*16 + r;
        int site = s0 + row;
        float2 v = make_float2(0.f, 0.f);
        if (site < nsites)
            v = *(const float2*)(X + ((size_t)site*8 + leaf)*64 + lane*2);
        uint32_t hi, lo;
        split_pair(v.x, v.y, hi, lo);
        uint32_t off = (uint32_t)(row*RS + lane*2)*2u;
        *(uint32_t*)(sm + dst + off)         = hi;
        *(uint32_t*)(sm + dst + VHALF + off) = lo;
    }
    __syncwarp();
}

__global__ __launch_bounds__(256, 1)
void tree_kernel(const float* __restrict__ X, float* __restrict__ out, int nsites)
{
    char* sm = dyn_smem;
    const int t    = threadIdx.x;
    const int w    = t >> 5;
    const int lane = t & 31;
    const int m    = blockIdx.x;              // component fastest -> L2 reuse of X
    const int s0   = blockIdx.y * 128;

    // stage P matrices (row-major, padded to RS) + pi
#pragma unroll
    for (int k = 0; k < 4; k++) {
        for (int idx = t; idx < 2048; idx += 256) {
            int c = idx >> 5, wi = idx & 31;
            uint32_t off = OFF_P + (uint32_t)k*PMAT + (uint32_t)(c*36 + wi)*4u;
            *(uint32_t*)(sm + off)         = g_Ph[k][m][idx];
            *(uint32_t*)(sm + off + PHALF) = g_Pl[k][m][idx];
        }
    }
    if (t < SDIM) ((float*)(sm + OFF_PI))[t] = g_pi[m][t];
    __syncthreads();

    // ---- node 8: leaves 0 (P1), 1 (P2) -> Ma ----
    stage_leaf(X, sm, OFF_V0, s0, 0, nsites, w, lane);
    stage_leaf(X, sm, OFF_V1, s0, 1, nsites, w, lane);
    do_node(sm, OFF_V0, 0, OFF_V1, 1, OFF_MA, w, lane);

    // ---- node 9: leaves 2 (P3), 3 (P4) -> Mb ----
    stage_leaf(X, sm, OFF_V0, s0, 2, nsites, w, lane);
    stage_leaf(X, sm, OFF_V1, s0, 3, nsites, w, lane);
    do_node(sm, OFF_V0, 2, OFF_V1, 3, OFF_MB, w, lane);

    // ---- node 12: A8 (P1), A9 (P2) -> Ma ----
    do_node(sm, OFF_MA, 0, OFF_MB, 1, OFF_MA, w, lane);

    // ---- node 10: leaves 4 (P1), 5 (P2) -> Mb ----
    stage_leaf(X, sm, OFF_V0, s0, 4, nsites, w, lane);
    stage_leaf(X, sm, OFF_V1, s0, 5, nsites, w, lane);
    do_node(sm, OFF_V0, 0, OFF_V1, 1, OFF_MB, w, lane);

    // ---- node 11: leaves 6 (P3), 7 (P4) -> V0 ----
    stage_leaf(X, sm, OFF_V0, s0, 6, nsites, w, lane);
    stage_leaf(X, sm, OFF_V1, s0, 7, nsites, w, lane);
    do_node(sm, OFF_V0, 2, OFF_V1, 3, OFF_V0, w, lane);

    // ---- node 13: A10 (P3), A11 (P4) -> Mb ----
    do_node(sm, OFF_MB, 2, OFF_V0, 3, OFF_MB, w, lane);

    // ---- root 14: A12 (P1), A13 (P2), marginalize against pi ----
    {
        float acc0[8][4], acc1[8][4];
#pragma unroll
        for (int n = 0; n < 8; n++)
#pragma unroll
            for (int q = 0; q < 4; q++) { acc0[n][q] = 0.f; acc1[n][q] = 0.f; }
        matvec(sm, OFF_MA, OFF_P + 0u*PMAT, acc0, w, lane);
        matvec(sm, OFF_MB, OFF_P + 1u*PMAT, acc1, w, lane);

        const int g  = lane >> 2;
        const int i2 = (lane & 3)*2;
        const float* pi = (const float*)(sm + OFF_PI);
        float sA = 0.f, sB = 0.f;                  // rows g and g+8
#pragma unroll
        for (int n = 0; n < 8; n++) {
            float p0 = pi[n*8 + i2], p1 = pi[n*8 + i2 + 1];
            sA += acc0[n][0]*acc1[n][0]*p0 + acc0[n][1]*acc1[n][1]*p1;
            sB += acc0[n][2]*acc1[n][2]*p0 + acc0[n][3]*acc1[n][3]*p1;
        }
        sA += __shfl_xor_sync(0xffffffffu, sA, 1);
        sA += __shfl_xor_sync(0xffffffffu, sA, 2);
        sB += __shfl_xor_sync(0xffffffffu, sB, 1);
        sB += __shfl_xor_sync(0xffffffffu, sB, 2);
        if ((lane & 3) == 0) {
            int siteA = s0 + w*16 + g;
            int siteB = siteA + 8;
            if (siteA < nsites) out[(size_t)siteA*MCOMP + m] = sA;
            if (siteB < nsites) out[(size_t)siteB*MCOMP + m] = sB;
        }
    }
}

// ==========================================================================
// kernel_launch
// ==========================================================================
extern "C" void kernel_launch(void* const* d_in, const int* in_sizes, int n_in,
                              void* d_out, int out_size)
{
    const float* X      = (const float*)d_in[0];
    const float* rates  = (const float*)d_in[1];
    const float* pi_inv = (const float*)d_in[2];
    float* out = (float*)d_out;
    const int nsites = in_sizes[0] / (8*64);

    const size_t expm_smem = 4*4096*sizeof(float);  // 64 KB

    cudaFuncSetAttribute(expm_kernel, cudaFuncAttributeMaxDynamicSharedMemorySize, (int)expm_smem);
    cudaFuncSetAttribute(tree_kernel, cudaFuncAttributeMaxDynamicSharedMemorySize, (int)SMEM_TREE);

    build_q_kernel<<<MCOMP, 256>>>(rates, pi_inv);
    expm_kernel<<<MCOMP, 256, expm_smem>>>();

    dim3 grid(MCOMP, (nsites + 127)/128);
    tree_kernel<<<grid, 256, SMEM_TREE>>>(X, out, nsites);
}

// round 13
// speedup vs baseline: 4.3343x; 3.4563x over previous
#include <cuda_runtime.h>
#include <cuda_bf16.h>
#include <cstdint>

#define MCOMP 8
#define SDIM 64
#define NPAIR (SDIM*(SDIM-1)/2)

// -------------------- device globals (setup products) --------------------
__device__ float g_pi[MCOMP][SDIM];                      // stationary distribution
// P matrices row-major [c][d] as packed bf16 pairs (u32), hi and lo planes
__device__ __align__(16) uint32_t g_Ph[4][MCOMP][2048];
__device__ __align__(16) uint32_t g_Pl[4][MCOMP][2048];

// single shared dynamic-smem symbol for all kernels in this TU
extern __shared__ char dyn_smem[];

// -------------------- helpers --------------------
__device__ __forceinline__ uint32_t smem_u32(const void* p) {
    uint32_t a;
    asm("{ .reg .u64 t; cvta.to.shared.u64 t, %1; cvt.u32.u64 %0, t; }" : "=r"(a) : "l"(p));
    return a;
}
__device__ __forceinline__ uint32_t pack2(__nv_bfloat16 a, __nv_bfloat16 b) {
    return (uint32_t)__bfloat16_as_ushort(a) | ((uint32_t)__bfloat16_as_ushort(b) << 16);
}
__device__ __forceinline__ void split_pair(float a, float b, uint32_t& hi, uint32_t& lo) {
    __nv_bfloat16 ha = __float2bfloat16(a), hb = __float2bfloat16(b);
    __nv_bfloat16 la = __float2bfloat16(a - __bfloat162float(ha));
    __nv_bfloat16 lb = __float2bfloat16(b - __bfloat162float(hb));
    hi = pack2(ha, hb);
    lo = pack2(la, lb);
}
__device__ __forceinline__ void mma16816(float* c,
                                         uint32_t a0, uint32_t a1, uint32_t a2, uint32_t a3,
                                         uint32_t b0, uint32_t b1) {
    asm volatile(
        "mma.sync.aligned.m16n8k16.row.col.f32.bf16.bf16.f32 "
        "{%0,%1,%2,%3}, {%4,%5,%6,%7}, {%8,%9}, {%0,%1,%2,%3};"
        : "+f"(c[0]), "+f"(c[1]), "+f"(c[2]), "+f"(c[3])
        : "r"(a0), "r"(a1), "r"(a2), "r"(a3), "r"(b0), "r"(b1));
}
__device__ __forceinline__ void ldsm4(uint32_t& r0, uint32_t& r1, uint32_t& r2, uint32_t& r3,
                                      uint32_t addr) {
    asm volatile("ldmatrix.sync.aligned.m8n8.x4.shared.b16 {%0,%1,%2,%3}, [%4];"
                 : "=r"(r0), "=r"(r1), "=r"(r2), "=r"(r3) : "r"(addr));
}

// ==========================================================================
// Kernel 1 (setup): build Q + expm (Taylor-12, s=3) + powers -> split bf16
// One CTA (256 threads) per mixture component. 2 launches/replay total so
// ncu -s 5 lands on tree_kernel.
// ==========================================================================
__device__ __forceinline__ void mm64(const float* __restrict__ A,
                                     const float* __restrict__ B,
                                     float* __restrict__ C, float alpha)
{
    const int t  = threadIdx.x;
    const int j  = t & 63;
    const int rg = t >> 6;
    float c[16];
#pragma unroll
    for (int ii = 0; ii < 16; ii++) c[ii] = 0.f;
    for (int d = 0; d < SDIM; d++) {
        float b = B[d*SDIM + j];
#pragma unroll
        for (int ii = 0; ii < 16; ii++)
            c[ii] += A[(rg*16 + ii)*SDIM + d]*b;
    }
#pragma unroll
    for (int ii = 0; ii < 16; ii++) C[(rg*16 + ii)*SDIM + j] = alpha*c[ii];
}

__device__ __forceinline__ void storeP(int k, int m, const float* __restrict__ buf)
{
    const int t = threadIdx.x;
    for (int idx = t; idx < 2048; idx += 256) {
        int c = idx >> 5, d = (idx & 31)*2;       // row-major [c][d], d contiguous
        uint32_t hi, lo;
        split_pair(buf[c*64 + d], buf[c*64 + d + 1], hi, lo);
        g_Ph[k][m][idx] = hi;
        g_Pl[k][m][idx] = lo;
    }
}

__global__ void setup_kernel(const float* __restrict__ rates,
                             const float* __restrict__ pi_inv)
{
    float* smf = (float*)dyn_smem;
    float* Bm  = smf;
    float* sum = smf + 4096;
    float* b0  = smf + 2*4096;
    float* b1  = smf + 3*4096;

    __shared__ float spi[SDIM];
    __shared__ float srow[SDIM];
    __shared__ float sns, semut;

    const int m = blockIdx.x;
    const int t = threadIdx.x;
    const float* y = pi_inv + m*(SDIM-1);

    // ---- build Q (scaled) into Bm ----
    if (t == 0) {
        float ns = 0.f;
        for (int j = 0; j < SDIM-1; j++) { float v = y[j]; ns += v*v; }
        sns = ns;
    }
    __syncthreads();
    const float ns  = sns;
    const float inv = 1.f/(ns + 1.f);
    if (t < SDIM) {
        float p = (t < SDIM-1) ? (2.f*y[t]*inv) : ((ns - 1.f)*inv);
        spi[t] = p*p;
    }
    __syncthreads();

    const float* rm = rates + m*NPAIR;
    for (int idx = t; idx < SDIM*SDIM; idx += 256) {
        int i = idx >> 6, j = idx & 63;
        float v = 0.f;
        if (i != j) {
            int a = i < j ? i : j;
            int b = i < j ? j : i;
            int lin = a*(2*SDIM - a - 1)/2 + (b - a - 1);   // np.triu_indices order
            float r = rm[lin];
            v = r*r*spi[j];
        }
        Bm[idx] = v;
    }
    __syncthreads();
    if (t < SDIM) {
        float s = 0.f;
        for (int j = 0; j < SDIM; j++) s += Bm[t*SDIM + j];
        srow[t] = s;
    }
    __syncthreads();
    if (t == 0) {
        float e = 0.f;
        for (int i = 0; i < SDIM; i++) e += spi[i]*srow[i];
        semut = e;
    }
    __syncthreads();
    const float scale = 0.05f/(8.f*semut);   // fold t_base=0.05 and 2^-3 expm scaling
    for (int idx = t; idx < SDIM*SDIM; idx += 256) {
        int i = idx >> 6;
        float v = (i == (idx & 63)) ? -srow[i] : Bm[idx];
        Bm[idx] = v*scale;
    }
    if (t < SDIM) g_pi[m][t] = spi[t];
    __syncthreads();

    // ---- Taylor-12 + 3 squarings + powers ----
    for (int idx = t; idx < 4096; idx += 256) {
        float b = Bm[idx];
        int i = idx >> 6, j = idx & 63;
        sum[idx] = b + (i == j ? 1.f : 0.f);
        b0[idx]  = b;
    }
    __syncthreads();

    float* cur = b0;
    float* nxt = b1;
    for (int k = 2; k <= 12; k++) {
        mm64(cur, Bm, nxt, 1.f/(float)k);
        __syncthreads();
        for (int idx = t; idx < 4096; idx += 256) sum[idx] += nxt[idx];
        float* tmp = cur; cur = nxt; nxt = tmp;
        __syncthreads();
    }
    mm64(sum, sum, cur, 1.f); __syncthreads();
    mm64(cur, cur, nxt, 1.f); __syncthreads();
    mm64(nxt, nxt, sum, 1.f); __syncthreads();
    storeP(0, m, sum);                          // P1 (t=0.05)
    __syncthreads();
    mm64(sum, sum, cur, 1.f); __syncthreads();  // cur = P2
    storeP(1, m, cur);
    __syncthreads();
    mm64(cur, sum, nxt, 1.f); __syncthreads();  // nxt = P3 = P2*P1
    storeP(2, m, nxt);
    __syncthreads();
    mm64(cur, cur, nxt, 1.f); __syncthreads();  // nxt = P4 = P2*P2
    storeP(3, m, nxt);
}

// ==========================================================================
// Kernel 2: mma.sync Felsenstein pruning, register-resident messages.
// One CTA = (component, 256-site tile), 512 threads = 16 warps x 16 rows.
//
// SMEM (row stride 72 bf16 = 144 B = 36 words; 36 % 32 == 4 -> ldmatrix rows
// hit disjoint bank groups, conflict-free):
//   P:  4 x (hi 64x72 + lo 64x72)  = 73728 B
//   Ma: 256x72 hi + lo             = 73728 B
//   Mb: 256x72 hi + lo             = 73728 B
//   pi: 64 floats
// ==========================================================================
#define RS     72
#define ROWB   144
#define PHALF  (64*ROWB)             // 9216
#define PMAT   (2*PHALF)             // 18432
#define VHALF  (256*ROWB)            // 36864
#define OFF_P   0u
#define OFF_MA  73728u
#define OFF_MB  147456u
#define OFF_PI  221184u
#define SMEM_TREE 221440u

// inner product step for one ks: given A frags (hi/lo), sweep all 8 n-columns
__device__ __forceinline__ void mma_ks(float acc[8][4],
                                       const uint32_t aH[4], const uint32_t aL[4],
                                       uint32_t pbase, int ks, uint32_t bFragOff)
{
#pragma unroll
    for (int np = 0; np < 4; np++) {
        uint32_t bh0,bh1,bh2,bh3, bl0,bl1,bl2,bl3;
        uint32_t baddr = pbase + (uint32_t)(np*2304 + ks*32) + bFragOff;
        ldsm4(bh0,bh1,bh2,bh3, baddr);
        ldsm4(bl0,bl1,bl2,bl3, baddr + PHALF);
        mma16816(acc[2*np],   aH[0],aH[1],aH[2],aH[3], bh0,bh1);
        mma16816(acc[2*np],   aL[0],aL[1],aL[2],aL[3], bh0,bh1);
        mma16816(acc[2*np],   aH[0],aH[1],aH[2],aH[3], bl0,bl1);
        mma16816(acc[2*np+1], aH[0],aH[1],aH[2],aH[3], bh2,bh3);
        mma16816(acc[2*np+1], aL[0],aL[1],aL[2],aL[3], bh2,bh3);
        mma16816(acc[2*np+1], aH[0],aH[1],aH[2],aH[3], bl2,bl3);
    }
}

__device__ __forceinline__ void zero_acc(float acc[8][4]) {
#pragma unroll
    for (int n = 0; n < 8; n++)
#pragma unroll
        for (int q = 0; q < 4; q++) acc[n][q] = 0.f;
}

// child matvec, A = message in smem buffer
__device__ __forceinline__ void matvec_smem(float acc[8][4], uint32_t sb, uint32_t bufOff,
                                            uint32_t pOff, uint32_t aFragOff, uint32_t bFragOff)
{
    zero_acc(acc);
#pragma unroll
    for (int ks = 0; ks < 4; ks++) {
        uint32_t aH[4], aL[4];
        uint32_t aaddr = sb + bufOff + (uint32_t)(ks*32) + aFragOff;
        ldsm4(aH[0],aH[1],aH[2],aH[3], aaddr);
        ldsm4(aL[0],aL[1],aL[2],aL[3], aaddr + VHALF);
        mma_ks(acc, aH, aL, sb + pOff, ks, bFragOff);
    }
}

// child matvec, A = message in registers (A-frag layout)
__device__ __forceinline__ void matvec_regA(float acc[8][4],
                                            const uint32_t mH[4][4], const uint32_t mL[4][4],
                                            uint32_t sb, uint32_t pOff, uint32_t bFragOff)
{
    zero_acc(acc);
#pragma unroll
    for (int ks = 0; ks < 4; ks++)
        mma_ks(acc, mH[ks], mL[ks], sb + pOff, ks, bFragOff);
}

// child matvec, A = leaf loaded directly from global X
__device__ __forceinline__ void matvec_leaf(float acc[8][4], const float* __restrict__ X,
                                            int s0, int w, int lane, int leaf, int nsites,
                                            uint32_t sb, uint32_t pOff, uint32_t bFragOff)
{
    const int g  = lane >> 2;
    const int i2 = (lane & 3)*2;
    const int site0 = s0 + w*16 + g;
    const bool ok0 = site0 < nsites;
    const bool ok1 = (site0 + 8) < nsites;
    const float* p0 = X + ((size_t)site0*8 + leaf)*64 + i2;
    const float* p1 = p0 + (size_t)8*8*64;
    const float2 z = make_float2(0.f, 0.f);

    float2 v[4][4];
#pragma unroll
    for (int ks = 0; ks < 4; ks++) {
        v[ks][0] = ok0 ? *(const float2*)(p0 + ks*16)     : z;
        v[ks][1] = ok1 ? *(const float2*)(p1 + ks*16)     : z;
        v[ks][2] = ok0 ? *(const float2*)(p0 + ks*16 + 8) : z;
        v[ks][3] = ok1 ? *(const float2*)(p1 + ks*16 + 8) : z;
    }
    zero_acc(acc);
#pragma unroll
    for (int ks = 0; ks < 4; ks++) {
        uint32_t aH[4], aL[4];
#pragma unroll
        for (int q = 0; q < 4; q++) split_pair(v[ks][q].x, v[ks][q].y, aH[q], aL[q]);
        mma_ks(acc, aH, aL, sb + pOff, ks, bFragOff);
    }
}

// Felsenstein product -> split bf16 -> store to smem buffer (A-frag layout)
__device__ __forceinline__ void prod_store(char* sm, uint32_t bufOff,
                                           const float a0[8][4], const float a1[8][4],
                                           int w, int lane)
{
    const int g  = lane >> 2;
    const int i2 = (lane & 3)*2;
    char* r0 = sm + bufOff + (uint32_t)(w*16 + g)*ROWB + i2*2;
#pragma unroll
    for (int ks = 0; ks < 4; ks++) {
        const int n0 = 2*ks, n1 = 2*ks + 1;
        uint32_t h, l;
        split_pair(a0[n0][0]*a1[n0][0], a0[n0][1]*a1[n0][1], h, l);
        *(uint32_t*)(r0 + ks*32)                     = h;
        *(uint32_t*)(r0 + ks*32 + VHALF)             = l;
        split_pair(a0[n0][2]*a1[n0][2], a0[n0][3]*a1[n0][3], h, l);
        *(uint32_t*)(r0 + 8*ROWB + ks*32)            = h;
        *(uint32_t*)(r0 + 8*ROWB + ks*32 + VHALF)    = l;
        split_pair(a0[n1][0]*a1[n1][0], a0[n1][1]*a1[n1][1], h, l);
        *(uint32_t*)(r0 + ks*32 + 16)                = h;
        *(uint32_t*)(r0 + ks*32 + 16 + VHALF)        = l;
        split_pair(a0[n1][2]*a1[n1][2], a0[n1][3]*a1[n1][3], h, l);
        *(uint32_t*)(r0 + 8*ROWB + ks*32 + 16)       = h;
        *(uint32_t*)(r0 + 8*ROWB + ks*32 + 16 + VHALF) = l;
    }
    __syncwarp();
}

// Felsenstein product -> split bf16 -> keep in registers as next-level A frags
__device__ __forceinline__ void prod_keep(uint32_t mH[4][4], uint32_t mL[4][4],
                                          const float a0[8][4], const float a1[8][4])
{
#pragma unroll
    for (int ks = 0; ks < 4; ks++) {
        const int n0 = 2*ks, n1 = 2*ks + 1;
        split_pair(a0[n0][0]*a1[n0][0], a0[n0][1]*a1[n0][1], mH[ks][0], mL[ks][0]);
        split_pair(a0[n0][2]*a1[n0][2], a0[n0][3]*a1[n0][3], mH[ks][1], mL[ks][1]);
        split_pair(a0[n1][0]*a1[n1][0], a0[n1][1]*a1[n1][1], mH[ks][2], mL[ks][2]);
        split_pair(a0[n1][2]*a1[n1][2], a0[n1][3]*a1[n1][3], mH[ks][3], mL[ks][3]);
    }
}

__global__ __launch_bounds__(512, 1)
void tree_kernel(const float* __restrict__ X, float* __restrict__ out, int nsites)
{
    char* sm = dyn_smem;
    const uint32_t sb = smem_u32(sm);
    const int t    = threadIdx.x;
    const int w    = t >> 5;
    const int lane = t & 31;
    const int m    = blockIdx.x;              // component fastest -> L2 reuse of X
    const int s0   = blockIdx.y * 256;

    // per-lane ldmatrix fragment offsets
    const uint32_t aFragOff = (uint32_t)((w*16 + (lane & 7) + ((lane >> 3) & 1)*8)*ROWB
                                         + (lane >> 4)*16);
    const uint32_t bFragOff = (uint32_t)((((lane >> 4)*8 + (lane & 7))*ROWB)
                                         + ((lane >> 3) & 1)*16);

    // stage P matrices + pi
#pragma unroll
    for (int k = 0; k < 4; k++) {
        for (int idx = t; idx < 2048; idx += 512) {
            int c = idx >> 5, wi = idx & 31;
            uint32_t off = OFF_P + (uint32_t)k*PMAT + (uint32_t)(c*ROWB + wi*4);
            *(uint32_t*)(sm + off)         = g_Ph[k][m][idx];
            *(uint32_t*)(sm + off + PHALF) = g_Pl[k][m][idx];
        }
    }
    if (t < SDIM) ((float*)(sm + OFF_PI))[t] = g_pi[m][t];
    __syncthreads();

    float acc0[8][4], acc1[8][4];
    uint32_t mH[4][4], mL[4][4];

    // ---- node 8: leaves 0 (P1), 1 (P2) -> Ma ----
    matvec_leaf(acc0, X, s0, w, lane, 0, nsites, sb, OFF_P + 0u*PMAT, bFragOff);
    matvec_leaf(acc1, X, s0, w, lane, 1, nsites, sb, OFF_P + 1u*PMAT, bFragOff);
    prod_store(sm, OFF_MA, acc0, acc1, w, lane);

    // ---- node 9: leaves 2 (P3), 3 (P4) -> regs M9 ----
    matvec_leaf(acc0, X, s0, w, lane, 2, nsites, sb, OFF_P + 2u*PMAT, bFragOff);
    matvec_leaf(acc1, X, s0, w, lane, 3, nsites, sb, OFF_P + 3u*PMAT, bFragOff);
    prod_keep(mH, mL, acc0, acc1);

    // ---- node 12: A8 (Ma, P1), A9 (regs, P2) -> Ma ----
    matvec_smem(acc0, sb, OFF_MA, OFF_P + 0u*PMAT, aFragOff, bFragOff);
    matvec_regA(acc1, mH, mL, sb, OFF_P + 1u*PMAT, bFragOff);
    prod_store(sm, OFF_MA, acc0, acc1, w, lane);

    // ---- node 10: leaves 4 (P1), 5 (P2) -> Mb ----
    matvec_leaf(acc0, X, s0, w, lane, 4, nsites, sb, OFF_P + 0u*PMAT, bFragOff);
    matvec_leaf(acc1, X, s0, w, lane, 5, nsites, sb, OFF_P + 1u*PMAT, bFragOff);
    prod_store(sm, OFF_MB, acc0, acc1, w, lane);

    // ---- node 11: leaves 6 (P3), 7 (P4) -> regs M11 ----
    matvec_leaf(acc0, X, s0, w, lane, 6, nsites, sb, OFF_P + 2u*PMAT, bFragOff);
    matvec_leaf(acc1, X, s0, w, lane, 7, nsites, sb, OFF_P + 3u*PMAT, bFragOff);
    prod_keep(mH, mL, acc0, acc1);

    // ---- node 13: A10 (Mb, P3), A11 (regs, P4) -> regs M13 ----
    matvec_smem(acc0, sb, OFF_MB, OFF_P + 2u*PMAT, aFragOff, bFragOff);
    matvec_regA(acc1, mH, mL, sb, OFF_P + 3u*PMAT, bFragOff);
    prod_keep(mH, mL, acc0, acc1);

    // ---- root 14: A12 (Ma, P1), A13 (regs, P2), marginalize against pi ----
    matvec_smem(acc0, sb, OFF_MA, OFF_P + 0u*PMAT, aFragOff, bFragOff);
    matvec_regA(acc1, mH, mL, sb, OFF_P + 1u*PMAT, bFragOff);
    {
        const int g  = lane >> 2;
        const int i2 = (lane & 3)*2;
        const float* pi = (const float*)(sm + OFF_PI);
        float sA = 0.f, sB = 0.f;                  // rows g and g+8
#pragma unroll
        for (int n = 0; n < 8; n++) {
            float p0 = pi[n*8 + i2], p1 = pi[n*8 + i2 + 1];
            sA += acc0[n][0]*acc1[n][0]*p0 + acc0[n][1]*acc1[n][1]*p1;
            sB += acc0[n][2]*acc1[n][2]*p0 + acc0[n][3]*acc1[n][3]*p1;
        }
        sA += __shfl_xor_sync(0xffffffffu, sA, 1);
        sA += __shfl_xor_sync(0xffffffffu, sA, 2);
        sB += __shfl_xor_sync(0xffffffffu, sB, 1);
        sB += __shfl_xor_sync(0xffffffffu, sB, 2);
        if ((lane & 3) == 0) {
            int siteA = s0 + w*16 + g;
            int siteB = siteA + 8;
            if (siteA < nsites) out[(size_t)siteA*MCOMP + m] = sA;
            if (siteB < nsites) out[(size_t)siteB*MCOMP + m] = sB;
        }
    }
}

// ==========================================================================
// kernel_launch
// ==========================================================================
extern "C" void kernel_launch(void* const* d_in, const int* in_sizes, int n_in,
                              void* d_out, int out_size)
{
    const float* X      = (const float*)d_in[0];
    const float* rates  = (const float*)d_in[1];
    const float* pi_inv = (const float*)d_in[2];
    float* out = (float*)d_out;
    const int nsites = in_sizes[0] / (8*64);

    const size_t setup_smem = 4*4096*sizeof(float);  // 64 KB

    cudaFuncSetAttribute(setup_kernel, cudaFuncAttributeMaxDynamicSharedMemorySize, (int)setup_smem);
    cudaFuncSetAttribute(tree_kernel,  cudaFuncAttributeMaxDynamicSharedMemorySize, (int)SMEM_TREE);

    setup_kernel<<<MCOMP, 256, setup_smem>>>(rates, pi_inv);

    dim3 grid(MCOMP, (nsites + 255)/256);
    tree_kernel<<<grid, 512, SMEM_TREE>>>(X, out, nsites);
}

// round 14
// speedup vs baseline: 4.3578x; 1.0054x over previous
#include <cuda_runtime.h>
#include <cuda_bf16.h>
#include <cstdint>

#define MCOMP 8
#define SDIM 64
#define NPAIR (SDIM*(SDIM-1)/2)

// -------------------- device globals (setup products) --------------------
__device__ float g_pi[MCOMP][SDIM];                      // stationary distribution
// P matrices row-major [c][d] as packed bf16 pairs (u32), hi and lo planes
__device__ __align__(16) uint32_t g_Ph[4][MCOMP][2048];
__device__ __align__(16) uint32_t g_Pl[4][MCOMP][2048];

// single shared dynamic-smem symbol for all kernels in this TU
extern __shared__ char dyn_smem[];

// -------------------- helpers --------------------
__device__ __forceinline__ uint32_t smem_u32(const void* p) {
    uint32_t a;
    asm("{ .reg .u64 t; cvta.to.shared.u64 t, %1; cvt.u32.u64 %0, t; }" : "=r"(a) : "l"(p));
    return a;
}
__device__ __forceinline__ uint32_t pack2(__nv_bfloat16 a, __nv_bfloat16 b) {
    return (uint32_t)__bfloat16_as_ushort(a) | ((uint32_t)__bfloat16_as_ushort(b) << 16);
}
__device__ __forceinline__ void split_pair(float a, float b, uint32_t& hi, uint32_t& lo) {
    __nv_bfloat16 ha = __float2bfloat16(a), hb = __float2bfloat16(b);
    __nv_bfloat16 la = __float2bfloat16(a - __bfloat162float(ha));
    __nv_bfloat16 lb = __float2bfloat16(b - __bfloat162float(hb));
    hi = pack2(ha, hb);
    lo = pack2(la, lb);
}
__device__ __forceinline__ void mma16816(float* c,
                                         uint32_t a0, uint32_t a1, uint32_t a2, uint32_t a3,
                                         uint32_t b0, uint32_t b1) {
    asm volatile(
        "mma.sync.aligned.m16n8k16.row.col.f32.bf16.bf16.f32 "
        "{%0,%1,%2,%3}, {%4,%5,%6,%7}, {%8,%9}, {%0,%1,%2,%3};"
        : "+f"(c[0]), "+f"(c[1]), "+f"(c[2]), "+f"(c[3])
        : "r"(a0), "r"(a1), "r"(a2), "r"(a3), "r"(b0), "r"(b1));
}
__device__ __forceinline__ void ldsm4(uint32_t& r0, uint32_t& r1, uint32_t& r2, uint32_t& r3,
                                      uint32_t addr) {
    asm volatile("ldmatrix.sync.aligned.m8n8.x4.shared.b16 {%0,%1,%2,%3}, [%4];"
                 : "=r"(r0), "=r"(r1), "=r"(r2), "=r"(r3) : "r"(addr));
}

// ==========================================================================
// Kernel 1 (setup): build Q + expm (Taylor-12, s=3) + powers -> split bf16
// One CTA (256 threads) per mixture component. 2 launches/replay total so
// ncu -s 5 lands on tree_kernel.
// ==========================================================================
__device__ __forceinline__ void mm64(const float* __restrict__ A,
                                     const float* __restrict__ B,
                                     float* __restrict__ C, float alpha)
{
    const int t  = threadIdx.x;
    const int j  = t & 63;
    const int rg = t >> 6;
    float c[16];
#pragma unroll
    for (int ii = 0; ii < 16; ii++) c[ii] = 0.f;
    for (int d = 0; d < SDIM; d++) {
        float b = B[d*SDIM + j];
#pragma unroll
        for (int ii = 0; ii < 16; ii++)
            c[ii] += A[(rg*16 + ii)*SDIM + d]*b;
    }
#pragma unroll
    for (int ii = 0; ii < 16; ii++) C[(rg*16 + ii)*SDIM + j] = alpha*c[ii];
}

__device__ __forceinline__ void storeP(int k, int m, const float* __restrict__ buf)
{
    const int t = threadIdx.x;
    for (int idx = t; idx < 2048; idx += 256) {
        int c = idx >> 5, d = (idx & 31)*2;       // row-major [c][d], d contiguous
        uint32_t hi, lo;
        split_pair(buf[c*64 + d], buf[c*64 + d + 1], hi, lo);
        g_Ph[k][m][idx] = hi;
        g_Pl[k][m][idx] = lo;
    }
}

__global__ void setup_kernel(const float* __restrict__ rates,
                             const float* __restrict__ pi_inv)
{
    float* smf = (float*)dyn_smem;
    float* Bm  = smf;
    float* sum = smf + 4096;
    float* b0  = smf + 2*4096;
    float* b1  = smf + 3*4096;

    __shared__ float spi[SDIM];
    __shared__ float srow[SDIM];
    __shared__ float sns, semut;

    const int m = blockIdx.x;
    const int t = threadIdx.x;
    const float* y = pi_inv + m*(SDIM-1);

    // ---- build Q (scaled) into Bm ----
    if (t == 0) {
        float ns = 0.f;
        for (int j = 0; j < SDIM-1; j++) { float v = y[j]; ns += v*v; }
        sns = ns;
    }
    __syncthreads();
    const float ns  = sns;
    const float inv = 1.f/(ns + 1.f);
    if (t < SDIM) {
        float p = (t < SDIM-1) ? (2.f*y[t]*inv) : ((ns - 1.f)*inv);
        spi[t] = p*p;
    }
    __syncthreads();

    const float* rm = rates + m*NPAIR;
    for (int idx = t; idx < SDIM*SDIM; idx += 256) {
        int i = idx >> 6, j = idx & 63;
        float v = 0.f;
        if (i != j) {
            int a = i < j ? i : j;
            int b = i < j ? j : i;
            int lin = a*(2*SDIM - a - 1)/2 + (b - a - 1);   // np.triu_indices order
            float r = rm[lin];
            v = r*r*spi[j];
        }
        Bm[idx] = v;
    }
    __syncthreads();
    if (t < SDIM) {
        float s = 0.f;
        for (int j = 0; j < SDIM; j++) s += Bm[t*SDIM + j];
        srow[t] = s;
    }
    __syncthreads();
    if (t == 0) {
        float e = 0.f;
        for (int i = 0; i < SDIM; i++) e += spi[i]*srow[i];
        semut = e;
    }
    __syncthreads();
    const float scale = 0.05f/(8.f*semut);   // fold t_base=0.05 and 2^-3 expm scaling
    for (int idx = t; idx < SDIM*SDIM; idx += 256) {
        int i = idx >> 6;
        float v = (i == (idx & 63)) ? -srow[i] : Bm[idx];
        Bm[idx] = v*scale;
    }
    if (t < SDIM) g_pi[m][t] = spi[t];
    __syncthreads();

    // ---- Taylor-12 + 3 squarings + powers ----
    for (int idx = t; idx < 4096; idx += 256) {
        float b = Bm[idx];
        int i = idx >> 6, j = idx & 63;
        sum[idx] = b + (i == j ? 1.f : 0.f);
        b0[idx]  = b;
    }
    __syncthreads();

    float* cur = b0;
    float* nxt = b1;
    for (int k = 2; k <= 12; k++) {
        mm64(cur, Bm, nxt, 1.f/(float)k);
        __syncthreads();
        for (int idx = t; idx < 4096; idx += 256) sum[idx] += nxt[idx];
        float* tmp = cur; cur = nxt; nxt = tmp;
        __syncthreads();
    }
    mm64(sum, sum, cur, 1.f); __syncthreads();
    mm64(cur, cur, nxt, 1.f); __syncthreads();
    mm64(nxt, nxt, sum, 1.f); __syncthreads();
    storeP(0, m, sum);                          // P1 (t=0.05)
    __syncthreads();
    mm64(sum, sum, cur, 1.f); __syncthreads();  // cur = P2
    storeP(1, m, cur);
    __syncthreads();
    mm64(cur, sum, nxt, 1.f); __syncthreads();  // nxt = P3 = P2*P1
    storeP(2, m, nxt);
    __syncthreads();
    mm64(cur, cur, nxt, 1.f); __syncthreads();  // nxt = P4 = P2*P2
    storeP(3, m, nxt);
}

// ==========================================================================
// Kernel 2: mma.sync Felsenstein pruning, register-resident messages.
// One CTA = (component, 256-site tile), 512 threads = 16 warps x 16 rows.
//
// SMEM (row stride 72 bf16 = 144 B = 36 words; 36 % 32 == 4 -> ldmatrix rows
// hit disjoint bank groups, conflict-free):
//   P:  4 x (hi 64x72 + lo 64x72)  = 73728 B
//   Ma: 256x72 hi + lo             = 73728 B
//   Mb: 256x72 hi + lo             = 73728 B
//   pi: 64 floats
// ==========================================================================
#define RS     72
#define ROWB   144
#define PHALF  (64*ROWB)             // 9216
#define PMAT   (2*PHALF)             // 18432
#define VHALF  (256*ROWB)            // 36864
#define OFF_P   0u
#define OFF_MA  73728u
#define OFF_MB  147456u
#define OFF_PI  221184u
#define SMEM_TREE 221440u

// inner product step for one ks: given A frags (hi/lo), sweep all 8 n-columns
__device__ __forceinline__ void mma_ks(float acc[8][4],
                                       const uint32_t aH[4], const uint32_t aL[4],
                                       uint32_t pbase, int ks, uint32_t bFragOff)
{
#pragma unroll
    for (int np = 0; np < 4; np++) {
        uint32_t bh0,bh1,bh2,bh3, bl0,bl1,bl2,bl3;
        uint32_t baddr = pbase + (uint32_t)(np*2304 + ks*32) + bFragOff;
        ldsm4(bh0,bh1,bh2,bh3, baddr);
        ldsm4(bl0,bl1,bl2,bl3, baddr + PHALF);
        mma16816(acc[2*np],   aH[0],aH[1],aH[2],aH[3], bh0,bh1);
        mma16816(acc[2*np],   aL[0],aL[1],aL[2],aL[3], bh0,bh1);
        mma16816(acc[2*np],   aH[0],aH[1],aH[2],aH[3], bl0,bl1);
        mma16816(acc[2*np+1], aH[0],aH[1],aH[2],aH[3], bh2,bh3);
        mma16816(acc[2*np+1], aL[0],aL[1],aL[2],aL[3], bh2,bh3);
        mma16816(acc[2*np+1], aH[0],aH[1],aH[2],aH[3], bl2,bl3);
    }
}

__device__ __forceinline__ void zero_acc(float acc[8][4]) {
#pragma unroll
    for (int n = 0; n < 8; n++)
#pragma unroll
        for (int q = 0; q < 4; q++) acc[n][q] = 0.f;
}

// child matvec, A = message in smem buffer
__device__ __forceinline__ void matvec_smem(float acc[8][4], uint32_t sb, uint32_t bufOff,
                                            uint32_t pOff, uint32_t aFragOff, uint32_t bFragOff)
{
    zero_acc(acc);
#pragma unroll
    for (int ks = 0; ks < 4; ks++) {
        uint32_t aH[4], aL[4];
        uint32_t aaddr = sb + bufOff + (uint32_t)(ks*32) + aFragOff;
        ldsm4(aH[0],aH[1],aH[2],aH[3], aaddr);
        ldsm4(aL[0],aL[1],aL[2],aL[3], aaddr + VHALF);
        mma_ks(acc, aH, aL, sb + pOff, ks, bFragOff);
    }
}

// child matvec, A = message in registers (A-frag layout)
__device__ __forceinline__ void matvec_regA(float acc[8][4],
                                            const uint32_t mH[4][4], const uint32_t mL[4][4],
                                            uint32_t sb, uint32_t pOff, uint32_t bFragOff)
{
    zero_acc(acc);
#pragma unroll
    for (int ks = 0; ks < 4; ks++)
        mma_ks(acc, mH[ks], mL[ks], sb + pOff, ks, bFragOff);
}

// child matvec, A = leaf loaded directly from global X
__device__ __forceinline__ void matvec_leaf(float acc[8][4], const float* __restrict__ X,
                                            int s0, int w, int lane, int leaf, int nsites,
                                            uint32_t sb, uint32_t pOff, uint32_t bFragOff)
{
    const int g  = lane >> 2;
    const int i2 = (lane & 3)*2;
    const int site0 = s0 + w*16 + g;
    const bool ok0 = site0 < nsites;
    const bool ok1 = (site0 + 8) < nsites;
    const float* p0 = X + ((size_t)site0*8 + leaf)*64 + i2;
    const float* p1 = p0 + (size_t)8*8*64;
    const float2 z = make_float2(0.f, 0.f);

    float2 v[4][4];
#pragma unroll
    for (int ks = 0; ks < 4; ks++) {
        v[ks][0] = ok0 ? *(const float2*)(p0 + ks*16)     : z;
        v[ks][1] = ok1 ? *(const float2*)(p1 + ks*16)     : z;
        v[ks][2] = ok0 ? *(const float2*)(p0 + ks*16 + 8) : z;
        v[ks][3] = ok1 ? *(const float2*)(p1 + ks*16 + 8) : z;
    }
    zero_acc(acc);
#pragma unroll
    for (int ks = 0; ks < 4; ks++) {
        uint32_t aH[4], aL[4];
#pragma unroll
        for (int q = 0; q < 4; q++) split_pair(v[ks][q].x, v[ks][q].y, aH[q], aL[q]);
        mma_ks(acc, aH, aL, sb + pOff, ks, bFragOff);
    }
}

// Felsenstein product -> split bf16 -> store to smem buffer (A-frag layout)
__device__ __forceinline__ void prod_store(char* sm, uint32_t bufOff,
                                           const float a0[8][4], const float a1[8][4],
                                           int w, int lane)
{
    const int g  = lane >> 2;
    const int i2 = (lane & 3)*2;
    char* r0 = sm + bufOff + (uint32_t)(w*16 + g)*ROWB + i2*2;
#pragma unroll
    for (int ks = 0; ks < 4; ks++) {
        const int n0 = 2*ks, n1 = 2*ks + 1;
        uint32_t h, l;
        split_pair(a0[n0][0]*a1[n0][0], a0[n0][1]*a1[n0][1], h, l);
        *(uint32_t*)(r0 + ks*32)                     = h;
        *(uint32_t*)(r0 + ks*32 + VHALF)             = l;
        split_pair(a0[n0][2]*a1[n0][2], a0[n0][3]*a1[n0][3], h, l);
        *(uint32_t*)(r0 + 8*ROWB + ks*32)            = h;
        *(uint32_t*)(r0 + 8*ROWB + ks*32 + VHALF)    = l;
        split_pair(a0[n1][0]*a1[n1][0], a0[n1][1]*a1[n1][1], h, l);
        *(uint32_t*)(r0 + ks*32 + 16)                = h;
        *(uint32_t*)(r0 + ks*32 + 16 + VHALF)        = l;
        split_pair(a0[n1][2]*a1[n1][2], a0[n1][3]*a1[n1][3], h, l);
        *(uint32_t*)(r0 + 8*ROWB + ks*32 + 16)       = h;
        *(uint32_t*)(r0 + 8*ROWB + ks*32 + 16 + VHALF) = l;
    }
    __syncwarp();
}

// Felsenstein product -> split bf16 -> keep in registers as next-level A frags
__device__ __forceinline__ void prod_keep(uint32_t mH[4][4], uint32_t mL[4][4],
                                          const float a0[8][4], const float a1[8][4])
{
#pragma unroll
    for (int ks = 0; ks < 4; ks++) {
        const int n0 = 2*ks, n1 = 2*ks + 1;
        split_pair(a0[n0][0]*a1[n0][0], a0[n0][1]*a1[n0][1], mH[ks][0], mL[ks][0]);
        split_pair(a0[n0][2]*a1[n0][2], a0[n0][3]*a1[n0][3], mH[ks][1], mL[ks][1]);
        split_pair(a0[n1][0]*a1[n1][0], a0[n1][1]*a1[n1][1], mH[ks][2], mL[ks][2]);
        split_pair(a0[n1][2]*a1[n1][2], a0[n1][3]*a1[n1][3], mH[ks][3], mL[ks][3]);
    }
}

__global__ __launch_bounds__(512, 1)
void tree_kernel(const float* __restrict__ X, float* __restrict__ out, int nsites)
{
    char* sm = dyn_smem;
    const uint32_t sb = smem_u32(sm);
    const int t    = threadIdx.x;
    const int w    = t >> 5;
    const int lane = t & 31;
    const int m    = blockIdx.x;              // component fastest -> L2 reuse of X
    const int s0   = blockIdx.y * 256;

    // per-lane ldmatrix fragment offsets
    const uint32_t aFragOff = (uint32_t)((w*16 + (lane & 7) + ((lane >> 3) & 1)*8)*ROWB
                                         + (lane >> 4)*16);
    const uint32_t bFragOff = (uint32_t)((((lane >> 4)*8 + (lane & 7))*ROWB)
                                         + ((lane >> 3) & 1)*16);

    // stage P matrices + pi
#pragma unroll
    for (int k = 0; k < 4; k++) {
        for (int idx = t; idx < 2048; idx += 512) {
            int c = idx >> 5, wi = idx & 31;
            uint32_t off = OFF_P + (uint32_t)k*PMAT + (uint32_t)(c*ROWB + wi*4);
            *(uint32_t*)(sm + off)         = g_Ph[k][m][idx];
            *(uint32_t*)(sm + off + PHALF) = g_Pl[k][m][idx];
        }
    }
    if (t < SDIM) ((float*)(sm + OFF_PI))[t] = g_pi[m][t];
    __syncthreads();

    float acc0[8][4], acc1[8][4];
    uint32_t mH[4][4], mL[4][4];

    // ---- node 8: leaves 0 (P1), 1 (P2) -> Ma ----
    matvec_leaf(acc0, X, s0, w, lane, 0, nsites, sb, OFF_P + 0u*PMAT, bFragOff);
    matvec_leaf(acc1, X, s0, w, lane, 1, nsites, sb, OFF_P + 1u*PMAT, bFragOff);
    prod_store(sm, OFF_MA, acc0, acc1, w, lane);

    // ---- node 9: leaves 2 (P3), 3 (P4) -> regs M9 ----
    matvec_leaf(acc0, X, s0, w, lane, 2, nsites, sb, OFF_P + 2u*PMAT, bFragOff);
    matvec_leaf(acc1, X, s0, w, lane, 3, nsites, sb, OFF_P + 3u*PMAT, bFragOff);
    prod_keep(mH, mL, acc0, acc1);

    // ---- node 12: A8 (Ma, P1), A9 (regs, P2) -> Ma ----
    matvec_smem(acc0, sb, OFF_MA, OFF_P + 0u*PMAT, aFragOff, bFragOff);
    matvec_regA(acc1, mH, mL, sb, OFF_P + 1u*PMAT, bFragOff);
    prod_store(sm, OFF_MA, acc0, acc1, w, lane);

    // ---- node 10: leaves 4 (P1), 5 (P2) -> Mb ----
    matvec_leaf(acc0, X, s0, w, lane, 4, nsites, sb, OFF_P + 0u*PMAT, bFragOff);
    matvec_leaf(acc1, X, s0, w, lane, 5, nsites, sb, OFF_P + 1u*PMAT, bFragOff);
    prod_store(sm, OFF_MB, acc0, acc1, w, lane);

    // ---- node 11: leaves 6 (P3), 7 (P4) -> regs M11 ----
    matvec_leaf(acc0, X, s0, w, lane, 6, nsites, sb, OFF_P + 2u*PMAT, bFragOff);
    matvec_leaf(acc1, X, s0, w, lane, 7, nsites, sb, OFF_P + 3u*PMAT, bFragOff);
    prod_keep(mH, mL, acc0, acc1);

    // ---- node 13: A10 (Mb, P3), A11 (regs, P4) -> regs M13 ----
    matvec_smem(acc0, sb, OFF_MB, OFF_P + 2u*PMAT, aFragOff, bFragOff);
    matvec_regA(acc1, mH, mL, sb, OFF_P + 3u*PMAT, bFragOff);
    prod_keep(mH, mL, acc0, acc1);

    // ---- root 14: A12 (Ma, P1), A13 (regs, P2), marginalize against pi ----
    matvec_smem(acc0, sb, OFF_MA, OFF_P + 0u*PMAT, aFragOff, bFragOff);
    matvec_regA(acc1, mH, mL, sb, OFF_P + 1u*PMAT, bFragOff);
    {
        const int g  = lane >> 2;
        const int i2 = (lane & 3)*2;
        const float* pi = (const float*)(sm + OFF_PI);
        float sA = 0.f, sB = 0.f;                  // rows g and g+8
#pragma unroll
        for (int n = 0; n < 8; n++) {
            float p0 = pi[n*8 + i2], p1 = pi[n*8 + i2 + 1];
            sA += acc0[n][0]*acc1[n][0]*p0 + acc0[n][1]*acc1[n][1]*p1;
            sB += acc0[n][2]*acc1[n][2]*p0 + acc0[n][3]*acc1[n][3]*p1;
        }
        sA += __shfl_xor_sync(0xffffffffu, sA, 1);
        sA += __shfl_xor_sync(0xffffffffu, sA, 2);
        sB += __shfl_xor_sync(0xffffffffu, sB, 1);
        sB += __shfl_xor_sync(0xffffffffu, sB, 2);
        if ((lane & 3) == 0) {
            int siteA = s0 + w*16 + g;
            int siteB = siteA + 8;
            if (siteA < nsites) out[(size_t)siteA*MCOMP + m] = sA;
            if (siteB < nsites) out[(size_t)siteB*MCOMP + m] = sB;
        }
    }
}

// ==========================================================================
// kernel_launch
// ==========================================================================
extern "C" void kernel_launch(void* const* d_in, const int* in_sizes, int n_in,
                              void* d_out, int out_size)
{
    const float* X      = (const float*)d_in[0];
    const float* rates  = (const float*)d_in[1];
    const float* pi_inv = (const float*)d_in[2];
    float* out = (float*)d_out;
    const int nsites = in_sizes[0] / (8*64);

    const size_t setup_smem = 4*4096*sizeof(float);  // 64 KB

    cudaFuncSetAttribute(setup_kernel, cudaFuncAttributeMaxDynamicSharedMemorySize, (int)setup_smem);
    cudaFuncSetAttribute(tree_kernel,  cudaFuncAttributeMaxDynamicSharedMemorySize, (int)SMEM_TREE);

    setup_kernel<<<MCOMP, 256, setup_smem>>>(rates, pi_inv);

    dim3 grid(MCOMP, (nsites + 255)/256);
    tree_kernel<<<grid, 512, SMEM_TREE>>>(X, out, nsites);
}